// round 1
// baseline (speedup 1.0000x reference)
#include <cuda_runtime.h>

// Problem constants (fixed for this registry problem instance)
#define BB 32
#define ZZ 384
#define NV 68
#define MC 46
#define DC 7
#define EE (MC*DC)          // 322
#define ZBLK 128
#define NZB (ZZ/ZBLK)       // 3

// Device scratch (no cudaMalloc allowed)
__device__ float    g_tot[BB*NV*ZZ];   // tot_plus = xa + sum(c2v), layout [b][n][z]
__device__ float    g_xaT[BB*NV*ZZ];   // transposed xa, layout [b][n][z]
__device__ unsigned g_msg[BB*MC*ZZ];   // packed check messages, layout [b][c][zm]
__device__ int      g_inv_off[NV+1];   // CSR: variable -> edges
__device__ int      g_inv_edge[EE];

// Packed msg word: bits[0:7)=raw v2c sign bits, bits[7:10)=argmin j,
// bits[10:16)=q1 (2*quant(w*min1), int6), bits[16:22)=q2 (int6).
__device__ __forceinline__ float unpack_c2v(unsigned p, int j) {
    int i1  = ((int)(p << 16)) >> 26;        // sign-extended bits 10..15
    int i2  = ((int)(p << 10)) >> 26;        // sign-extended bits 16..21
    int arg = (int)((p >> 7) & 7u);
    unsigned sb = p & 0x7fu;
    int base = (j == arg) ? i2 : i1;
    // extrinsic sign = parity of signs of OTHER edges = total parity ^ own bit
    int par = (__popc(sb) ^ (int)(sb >> j)) & 1;
    float v = (float)base * 0.5f;
    return par ? -v : v;
}

// ---------------------------------------------------------------------------
// Init: transpose xa -> g_xaT / g_tot, zero g_msg
// ---------------------------------------------------------------------------
__global__ void k_init(const float* __restrict__ xa) {
    int idx = blockIdx.x * blockDim.x + threadIdx.x;
    if (idx < BB*NV*ZZ) {
        int z = idx % ZZ;
        int t = idx / ZZ;
        int n = t % NV;
        int b = t / NV;
        float v = xa[(b*ZZ + z)*NV + n];
        g_xaT[idx] = v;
        g_tot[idx] = v;          // iteration 0: c2v = 0 -> tot_plus = xa
    }
    if (idx < BB*MC*ZZ) g_msg[idx] = 0u;   // unpacks to c2v = 0
}

// ---------------------------------------------------------------------------
// Build inverse index: variable n -> list of its edges (order irrelevant:
// half-integer sums are exact in fp32 in any order)
// ---------------------------------------------------------------------------
__global__ void k_build_inv(const int* __restrict__ vn) {
    __shared__ int off[NV+1];
    __shared__ int cur[NV];
    int t = threadIdx.x;
    for (int i = t; i <= NV; i += blockDim.x) off[i] = 0;
    __syncthreads();
    for (int e = t; e < EE; e += blockDim.x) atomicAdd(&off[vn[e] + 1], 1);
    __syncthreads();
    if (t == 0) {
        int s = 0;
        for (int i = 0; i <= NV; i++) { s += off[i]; off[i] = s; }
    }
    __syncthreads();
    for (int i = t; i <= NV; i += blockDim.x) g_inv_off[i] = off[i];
    for (int i = t; i <  NV; i += blockDim.x) cur[i] = off[i];
    __syncthreads();
    for (int e = t; e < EE; e += blockDim.x) {
        int p = atomicAdd(&cur[vn[e]], 1);
        g_inv_edge[p] = e;
    }
}

// ---------------------------------------------------------------------------
// Phase 2: check-node min-sum. One thread per (b, check c, row zm).
// Reads tot_plus at zv=(zm+shift)%Z (coalesced in transposed layout),
// old packed message; writes new packed message in place.
// ---------------------------------------------------------------------------
__global__ void __launch_bounds__(ZBLK) k_phase2(
    const int* __restrict__ vn, const int* __restrict__ sh,
    const float* __restrict__ cw, int it) {
    int bid = blockIdx.x;
    int zb = bid % NZB;
    int c  = (bid / NZB) % MC;
    int b  = bid / (NZB * MC);
    int zm = zb * ZBLK + threadIdx.x;

    __shared__ int s_n[DC], s_s[DC];
    if (threadIdx.x < DC) {
        int e = c * DC + threadIdx.x;
        s_n[threadIdx.x] = vn[e];
        s_s[threadIdx.x] = sh[e];
    }
    __syncthreads();

    unsigned oldw = g_msg[(b*MC + c)*ZZ + zm];
    float w = cw[it];

    // gather first (independent loads -> MLP)
    float tp[DC];
#pragma unroll
    for (int j = 0; j < DC; j++) {
        int zv = zm + s_s[j]; if (zv >= ZZ) zv -= ZZ;
        tp[j] = g_tot[(b*NV + s_n[j])*ZZ + zv];
    }

    float mn1 = 1e30f, mn2 = 1e30f;
    int arg = 0;
    unsigned sb = 0;
#pragma unroll
    for (int j = 0; j < DC; j++) {
        float x = tp[j] - unpack_c2v(oldw, j);
        x = fminf(fmaxf(x, -20.0f), 20.0f);
        if (x < 0.0f) sb |= (1u << j);
        float a = fabsf(x);
        if (a < mn1) { mn2 = mn1; mn1 = a; arg = j; }
        else         { mn2 = fminf(mn2, a); }
    }
    // quantize: clip(round(2*w*min)/2, +-7.5); rintf = round-half-even = jnp.round
    int q1 = (int)fminf(fmaxf(rintf(2.0f * (w * mn1)), -15.0f), 15.0f);
    int q2 = (int)fminf(fmaxf(rintf(2.0f * (w * mn2)), -15.0f), 15.0f);

    g_msg[(b*MC + c)*ZZ + zm] =
        sb | ((unsigned)arg << 7) | ((unsigned)(q1 & 63) << 10) | ((unsigned)(q2 & 63) << 16);
}

// ---------------------------------------------------------------------------
// Phase 1: variable-node sum. One thread per (b, variable n, row z).
// c2v sum accumulated separately (exact half-integer sum), then + xa once:
// bit-exact vs the JAX einsum + add.
// dst == nullptr -> internal g_tot; else final output (same [b][n][z] layout).
// ---------------------------------------------------------------------------
__global__ void __launch_bounds__(ZBLK) k_phase1(
    const int* __restrict__ sh, float* __restrict__ dst) {
    int bid = blockIdx.x;
    int zb = bid % NZB;
    int n  = (bid / NZB) % NV;
    int b  = bid / (NZB * NV);
    int z  = zb * ZBLK + threadIdx.x;

    __shared__ int s_e[16], s_sh[16];   // max variable degree << 16 here
    int k0 = g_inv_off[n], k1 = g_inv_off[n+1];
    int deg = k1 - k0;
    if (threadIdx.x < deg) {
        int e = g_inv_edge[k0 + threadIdx.x];
        s_e[threadIdx.x]  = e;
        s_sh[threadIdx.x] = sh[e];
    }
    __syncthreads();

    float s = 0.0f;
    for (int k = 0; k < deg; k++) {
        int e = s_e[k];
        int c = e / DC, j = e - c * DC;
        int zm = z - s_sh[k]; if (zm < 0) zm += ZZ;
        s += unpack_c2v(g_msg[(b*MC + c)*ZZ + zm], j);
    }
    int idx = (b*NV + n)*ZZ + z;
    float v = g_xaT[idx] + s;
    if (dst) dst[idx] = v;      // out[b, n*Z + z] == [b][n][z] layout
    else     g_tot[idx] = v;
}

// ---------------------------------------------------------------------------
extern "C" void kernel_launch(void* const* d_in, const int* in_sizes, int n_in,
                              void* d_out, int out_size) {
    const float* xa = (const float*)d_in[0];
    const float* cw = (const float*)d_in[1];
    const int*   vn = (const int*)d_in[2];
    // d_in[3] = cn_idx: structure is repeat(arange(M), dc) -> implicit (e/7)
    const int*   sh = (const int*)d_in[4];

    int iters = in_sizes[1];   // cn_weights length = 8

    int total = BB*NV*ZZ;
    k_init<<<(total + 255)/256, 256>>>(xa);
    k_build_inv<<<1, 256>>>(vn);

    for (int it = 0; it < iters; ++it) {
        k_phase2<<<BB*MC*NZB, ZBLK>>>(vn, sh, cw, it);
        k_phase1<<<BB*NV*NZB, ZBLK>>>(sh, (it == iters-1) ? (float*)d_out : (float*)nullptr);
    }
}

// round 4
// speedup vs baseline: 1.0769x; 1.0769x over previous
#include <cuda_runtime.h>

// Problem constants (fixed for this registry problem instance)
#define BB 32
#define ZZ 384
#define NV 68
#define MC 46
#define DC 7
#define EE (MC*DC)          // 322

// Device scratch (no cudaMalloc allowed)
__device__ float g_tot[BB*NV*ZZ];     // tot_plus = xa + sum(c2v), layout [b][n][z]
__device__ float g_xaT[BB*NV*ZZ];     // transposed xa, layout [b][n][z]
__device__ float g_c2v[BB*EE*ZZ];     // c2v messages as plain floats, layout [b][e][zm]
__device__ int   g_inv_off[NV+1];     // CSR: variable -> its edges
__device__ int   g_inv_eoff[EE];      // per edge (var-sorted): e*ZZ
__device__ int   g_inv_sh [EE];       // per edge (var-sorted): shift

// ---------------------------------------------------------------------------
// Init: transpose xa -> g_xaT / g_tot. (c2v needs no init: phase2 it==0
// substitutes old=0 and rewrites every entry each iteration.)
// ---------------------------------------------------------------------------
__global__ void k_init(const float* __restrict__ xa) {
    int idx = blockIdx.x * blockDim.x + threadIdx.x;
    if (idx < BB*NV*ZZ) {
        int z = idx % ZZ;
        int t = idx / ZZ;
        int n = t % NV;
        int b = t / NV;
        float v = xa[(b*ZZ + z)*NV + n];
        g_xaT[idx] = v;
        g_tot[idx] = v;          // iteration 0: c2v = 0 -> tot_plus = xa
    }
}

// ---------------------------------------------------------------------------
// Build inverse index: variable n -> list of (e*ZZ, shift).
// (Order irrelevant: half-integer sums are exact in fp32 in any order.)
// ---------------------------------------------------------------------------
__global__ void k_build_inv(const int* __restrict__ vn, const int* __restrict__ sh) {
    __shared__ int off[NV+1];
    __shared__ int cur[NV];
    int t = threadIdx.x;
    for (int i = t; i <= NV; i += blockDim.x) off[i] = 0;
    __syncthreads();
    for (int e = t; e < EE; e += blockDim.x) atomicAdd(&off[vn[e] + 1], 1);
    __syncthreads();
    if (t == 0) {
        int s = 0;
        for (int i = 0; i <= NV; i++) { s += off[i]; off[i] = s; }
    }
    __syncthreads();
    for (int i = t; i <= NV; i += blockDim.x) g_inv_off[i] = off[i];
    for (int i = t; i <  NV; i += blockDim.x) cur[i] = off[i];
    __syncthreads();
    for (int e = t; e < EE; e += blockDim.x) {
        int p = atomicAdd(&cur[vn[e]], 1);
        g_inv_eoff[p] = e * ZZ;
        g_inv_sh [p] = sh[e];
    }
}

// ---------------------------------------------------------------------------
// Phase 2: check-node min-sum. One block per (b, check c), 384 threads = zm.
// Reads tot_plus at zv=(zm+shift)%Z (coalesced rows, rotation only) and old
// c2v (own rows, immediate offsets j*ZZ), writes new signed quantized c2v.
// ---------------------------------------------------------------------------
__global__ void __launch_bounds__(ZZ) k_phase2(
    const int* __restrict__ vn, const int* __restrict__ sh,
    const float* __restrict__ cw, int it, int first) {
    int c = blockIdx.x % MC;
    int b = blockIdx.x / MC;
    int zm = threadIdx.x;

    __shared__ int s_n[DC], s_s[DC];
    if (threadIdx.x < DC) {
        int e = c * DC + threadIdx.x;
        s_n[threadIdx.x] = vn[e];
        s_s[threadIdx.x] = sh[e];
    }
    __syncthreads();

    const float* totb = g_tot + b*NV*ZZ;
    float*       cvb  = g_c2v + (b*EE + c*DC)*ZZ + zm;   // own rows: +j*ZZ
    float w = __ldg(cw + it);

    // gather tot first (independent loads -> MLP)
    float tp[DC];
#pragma unroll
    for (int j = 0; j < DC; j++) {
        int zv = zm + s_s[j]; if (zv >= ZZ) zv -= ZZ;
        tp[j] = totb[s_n[j]*ZZ + zv];
    }
    float old[DC];
#pragma unroll
    for (int j = 0; j < DC; j++) old[j] = first ? 0.0f : cvb[j*ZZ];

    float mn1 = 1e30f, mn2 = 1e30f;
    int arg = 0;
    unsigned sb = 0;
#pragma unroll
    for (int j = 0; j < DC; j++) {
        float x = tp[j] - old[j];
        x = fminf(fmaxf(x, -20.0f), 20.0f);
        if (x < 0.0f) sb |= (1u << j);
        float a = fabsf(x);
        if (a < mn1) { mn2 = mn1; mn1 = a; arg = j; }
        else         { mn2 = fminf(mn2, a); }
    }
    int par = __popc(sb) & 1;
    // quantize: clip(round(2*w*min)/2, +-7.5); rintf = round-half-even = jnp.round
    float mag1 = 0.5f * fminf(fmaxf(rintf(2.0f * (w * mn1)), -15.0f), 15.0f);
    float mag2 = 0.5f * fminf(fmaxf(rintf(2.0f * (w * mn2)), -15.0f), 15.0f);

#pragma unroll
    for (int j = 0; j < DC; j++) {
        float m = (j == arg) ? mag2 : mag1;               // branch-free SEL
        unsigned neg = (unsigned)((par ^ (int)(sb >> j)) & 1) << 31;  // extrinsic sign
        cvb[j*ZZ] = __uint_as_float(__float_as_uint(m) ^ neg);
    }
}

// ---------------------------------------------------------------------------
// Phase 1: variable-node sum. One block per (b, variable n), 384 threads = z.
// s = sum of c2v floats (exact half-integer sum), tot = xa + s: bit-exact vs
// JAX einsum + add. dst==nullptr -> g_tot; else final output (same layout).
// ---------------------------------------------------------------------------
__global__ void __launch_bounds__(ZZ) k_phase1(float* __restrict__ dst) {
    int n = blockIdx.x % NV;
    int b = blockIdx.x / NV;
    int z = threadIdx.x;

    __shared__ int s_eo[EE], s_sh2[EE];   // worst-case safe sizing (2.6KB)
    int k0 = g_inv_off[n], k1 = g_inv_off[n+1];
    int deg = k1 - k0;
    for (int i = threadIdx.x; i < deg; i += blockDim.x) {
        s_eo[i]  = g_inv_eoff[k0 + i];
        s_sh2[i] = g_inv_sh [k0 + i];
    }
    __syncthreads();

    const float* cvb = g_c2v + b*EE*ZZ;
    float s = 0.0f;
#pragma unroll 4
    for (int k = 0; k < deg; k++) {
        int zm = z - s_sh2[k]; if (zm < 0) zm += ZZ;
        s += cvb[s_eo[k] + zm];
    }
    int idx = (b*NV + n)*ZZ + z;
    float v = g_xaT[idx] + s;
    if (dst) dst[idx] = v;      // out[b, n*Z + z] == [b][n][z] layout
    else     g_tot[idx] = v;
}

// ---------------------------------------------------------------------------
extern "C" void kernel_launch(void* const* d_in, const int* in_sizes, int n_in,
                              void* d_out, int out_size) {
    const float* xa = (const float*)d_in[0];
    const float* cw = (const float*)d_in[1];
    const int*   vn = (const int*)d_in[2];
    // d_in[3] = cn_idx: structure is repeat(arange(M), dc) -> implicit (e/7)
    const int*   sh = (const int*)d_in[4];

    int iters = in_sizes[1];   // cn_weights length = 8

    int total = BB*NV*ZZ;
    k_init<<<(total + 255)/256, 256>>>(xa);
    k_build_inv<<<1, 256>>>(vn, sh);

    for (int it = 0; it < iters; ++it) {
        k_phase2<<<BB*MC, ZZ>>>(vn, sh, cw, it, it == 0);
        k_phase1<<<BB*NV, ZZ>>>((it == iters-1) ? (float*)d_out : (float*)nullptr);
    }
}

// round 5
// speedup vs baseline: 1.2489x; 1.1597x over previous
#include <cuda_runtime.h>

// Problem constants (fixed for this registry problem instance)
#define BB 32
#define ZZ 384
#define NV 68
#define MC 46
#define DC 7
#define EE (MC*DC)          // 322

// Device scratch (no cudaMalloc allowed)
__device__ float g_tot[BB*NV*ZZ];     // tot_plus = xa + sum(c2v), layout [b][n][z]
__device__ float g_xaT[BB*NV*ZZ];     // transposed xa, layout [b][n][z]
// c2v stored in VARIABLE z-domain: c2v_v[b][e][zv], zv=(zm+shift_e)%Z.
// Phase2 reads/writes it at the rotated index zv (same index as its tot read);
// phase1 reads it un-rotated and fully vectorized.
__device__ float g_c2v[BB*EE*ZZ];
__device__ int   g_inv_off[NV+1];     // CSR: variable -> its edges
__device__ int   g_inv_eoff[EE];      // per edge (var-sorted): e*ZZ

// ---------------------------------------------------------------------------
// Init: transpose xa -> g_xaT / g_tot. (c2v needs no init: phase2 it==0
// substitutes old=0 and rewrites every entry each iteration.)
// ---------------------------------------------------------------------------
__global__ void k_init(const float* __restrict__ xa) {
    int idx = blockIdx.x * blockDim.x + threadIdx.x;
    if (idx < BB*NV*ZZ) {
        int z = idx % ZZ;
        int t = idx / ZZ;
        int n = t % NV;
        int b = t / NV;
        float v = xa[(b*ZZ + z)*NV + n];
        g_xaT[idx] = v;
        g_tot[idx] = v;          // iteration 0: c2v = 0 -> tot_plus = xa
    }
}

// ---------------------------------------------------------------------------
// Build inverse index: variable n -> list of e*ZZ.
// (Order irrelevant: half-integer sums are exact in fp32 in any order.)
// ---------------------------------------------------------------------------
__global__ void k_build_inv(const int* __restrict__ vn) {
    __shared__ int off[NV+1];
    __shared__ int cur[NV];
    int t = threadIdx.x;
    for (int i = t; i <= NV; i += blockDim.x) off[i] = 0;
    __syncthreads();
    for (int e = t; e < EE; e += blockDim.x) atomicAdd(&off[vn[e] + 1], 1);
    __syncthreads();
    if (t == 0) {
        int s = 0;
        for (int i = 0; i <= NV; i++) { s += off[i]; off[i] = s; }
    }
    __syncthreads();
    for (int i = t; i <= NV; i += blockDim.x) g_inv_off[i] = off[i];
    for (int i = t; i <  NV; i += blockDim.x) cur[i] = off[i];
    __syncthreads();
    for (int e = t; e < EE; e += blockDim.x) {
        int p = atomicAdd(&cur[vn[e]], 1);
        g_inv_eoff[p] = e * ZZ;
    }
}

// ---------------------------------------------------------------------------
// Phase 2: check-node min-sum. One block per (b, check c), 384 threads = zm.
// Edge j uses rotated index zv_j=(zm+shift_j)%Z for tot read, old-c2v read,
// and new-c2v write (c2v lives in variable domain). All coalesced.
// ---------------------------------------------------------------------------
__global__ void __launch_bounds__(ZZ) k_phase2(
    const int* __restrict__ vn, const int* __restrict__ sh,
    const float* __restrict__ cw, int it, int first) {
    int c = blockIdx.x % MC;
    int b = blockIdx.x / MC;
    int zm = threadIdx.x;

    __shared__ int s_n[DC], s_s[DC];
    if (threadIdx.x < DC) {
        int e = c * DC + threadIdx.x;
        s_n[threadIdx.x] = vn[e];
        s_s[threadIdx.x] = sh[e];
    }
    __syncthreads();

    const float* totb = g_tot + b*NV*ZZ;
    float*       cvb  = g_c2v + (b*EE + c*DC)*ZZ;   // edge j row: + j*ZZ
    float w = __ldg(cw + it);

    int zv[DC];
#pragma unroll
    for (int j = 0; j < DC; j++) {
        int t2 = zm + s_s[j]; if (t2 >= ZZ) t2 -= ZZ;
        zv[j] = t2;
    }

    // gather tot + old c2v (independent loads -> MLP)
    float tp[DC], old[DC];
#pragma unroll
    for (int j = 0; j < DC; j++) tp[j]  = totb[s_n[j]*ZZ + zv[j]];
#pragma unroll
    for (int j = 0; j < DC; j++) old[j] = first ? 0.0f : cvb[j*ZZ + zv[j]];

    float mn1 = 1e30f, mn2 = 1e30f;
    int arg = 0;
    unsigned sb = 0;
#pragma unroll
    for (int j = 0; j < DC; j++) {
        float x = tp[j] - old[j];
        x = fminf(fmaxf(x, -20.0f), 20.0f);
        if (x < 0.0f) sb |= (1u << j);
        float a = fabsf(x);
        if (a < mn1) { mn2 = mn1; mn1 = a; arg = j; }
        else         { mn2 = fminf(mn2, a); }
    }
    int par = __popc(sb) & 1;
    // quantize: clip(round(2*w*min)/2, +-7.5); rintf = round-half-even = jnp.round
    float mag1 = 0.5f * fminf(fmaxf(rintf(2.0f * (w * mn1)), -15.0f), 15.0f);
    float mag2 = 0.5f * fminf(fmaxf(rintf(2.0f * (w * mn2)), -15.0f), 15.0f);

#pragma unroll
    for (int j = 0; j < DC; j++) {
        float m = (j == arg) ? mag2 : mag1;               // branch-free SEL
        unsigned neg = (unsigned)((par ^ (int)(sb >> j)) & 1) << 31;  // extrinsic sign
        cvb[j*ZZ + zv[j]] = __uint_as_float(__float_as_uint(m) ^ neg);
    }
}

// ---------------------------------------------------------------------------
// Phase 1: variable-node sum, fully vectorized. One block per (b, n),
// 96 threads, each thread owns 4 consecutive z (float4). All edge rows are
// read at plain offset z (no rotation -> 16B aligned). Sum of half-integer
// c2v is exact in any order; tot = xa + s in one rounded add: bit-exact.
// dst==nullptr -> g_tot; else final output (same [b][n][z] layout).
// ---------------------------------------------------------------------------
__global__ void __launch_bounds__(ZZ/4) k_phase1(float* __restrict__ dst) {
    int n = blockIdx.x % NV;
    int b = blockIdx.x / NV;
    int z4 = threadIdx.x * 4;

    __shared__ int s_eo[32];                 // deg << 32 always
    int k0 = g_inv_off[n], k1 = g_inv_off[n+1];
    int deg = k1 - k0;
    if (threadIdx.x < deg) s_eo[threadIdx.x] = g_inv_eoff[k0 + threadIdx.x];
    __syncthreads();

    const float* cvb = g_c2v + b*EE*ZZ;
    float4 s = make_float4(0.f, 0.f, 0.f, 0.f);
#pragma unroll 4
    for (int k = 0; k < deg; k++) {
        float4 v = *(const float4*)(cvb + s_eo[k] + z4);
        s.x += v.x; s.y += v.y; s.z += v.z; s.w += v.w;
    }
    int idx = (b*NV + n)*ZZ + z4;
    float4 xa4 = *(const float4*)(g_xaT + idx);
    float4 o = make_float4(xa4.x + s.x, xa4.y + s.y, xa4.z + s.z, xa4.w + s.w);
    if (dst) *(float4*)(dst + idx)   = o;    // out[b, n*Z + z] == [b][n][z]
    else     *(float4*)(g_tot + idx) = o;
}

// ---------------------------------------------------------------------------
extern "C" void kernel_launch(void* const* d_in, const int* in_sizes, int n_in,
                              void* d_out, int out_size) {
    const float* xa = (const float*)d_in[0];
    const float* cw = (const float*)d_in[1];
    const int*   vn = (const int*)d_in[2];
    // d_in[3] = cn_idx: structure is repeat(arange(M), dc) -> implicit (e/7)
    const int*   sh = (const int*)d_in[4];

    int iters = in_sizes[1];   // cn_weights length = 8

    int total = BB*NV*ZZ;
    k_init<<<(total + 255)/256, 256>>>(xa);
    k_build_inv<<<1, 256>>>(vn);

    for (int it = 0; it < iters; ++it) {
        k_phase2<<<BB*MC, ZZ>>>(vn, sh, cw, it, it == 0);
        k_phase1<<<BB*NV, ZZ/4>>>((it == iters-1) ? (float*)d_out : (float*)nullptr);
    }
}